// round 1
// baseline (speedup 1.0000x reference)
#include <cuda_runtime.h>
#include <math.h>

#define T_TOT 4096   // B*S tokens
#define HDIM  4096   // hidden size
#define SEQ   2048
#define NHEAD 32
#define DHEAD 128

// Scratch (device globals; no allocations allowed)
__device__ float g_q[(size_t)T_TOT * HDIM];
__device__ float g_k[(size_t)T_TOT * HDIM];
__device__ float g_v[(size_t)T_TOT * HDIM];
__device__ float g_att[(size_t)T_TOT * HDIM];

// ---------------------------------------------------------------------------
// TN SGEMM: C[m,n] = sum_k A[m,k] * W[n,k]   (A: MxK row-major, W: NxK row-major)
// BM=BN=128, BK=16, 256 threads, 8x8 per thread.
// ---------------------------------------------------------------------------
__global__ __launch_bounds__(256) void sgemm_tn(const float* __restrict__ A,
                                                const float* __restrict__ W,
                                                float* __restrict__ C) {
    const int K = HDIM, N = HDIM;
    __shared__ float As[16][132];
    __shared__ float Ws[16][132];

    const int tid = threadIdx.x;
    const int m0 = blockIdx.y * 128;
    const int n0 = blockIdx.x * 128;
    const int ty = tid >> 4;   // 0..15
    const int tx = tid & 15;   // 0..15

    const float* Aptr = A + (size_t)m0 * K;
    const float* Wptr = W + (size_t)n0 * K;

    float acc[8][8];
#pragma unroll
    for (int i = 0; i < 8; i++)
#pragma unroll
        for (int j = 0; j < 8; j++) acc[i][j] = 0.f;

    for (int k0 = 0; k0 < K; k0 += 16) {
#pragma unroll
        for (int it = 0; it < 2; it++) {
            int v = tid + it * 256;          // 0..511
            int row = v >> 2;                // 0..127
            int kq = (v & 3) << 2;           // 0,4,8,12
            float4 a = *(const float4*)(Aptr + (size_t)row * K + k0 + kq);
            As[kq + 0][row] = a.x; As[kq + 1][row] = a.y;
            As[kq + 2][row] = a.z; As[kq + 3][row] = a.w;
            float4 w = *(const float4*)(Wptr + (size_t)row * K + k0 + kq);
            Ws[kq + 0][row] = w.x; Ws[kq + 1][row] = w.y;
            Ws[kq + 2][row] = w.z; Ws[kq + 3][row] = w.w;
        }
        __syncthreads();

#pragma unroll
        for (int k = 0; k < 16; k++) {
            float ra[8], rb[8];
            *(float4*)&ra[0] = *(const float4*)&As[k][ty * 8];
            *(float4*)&ra[4] = *(const float4*)&As[k][ty * 8 + 4];
            *(float4*)&rb[0] = *(const float4*)&Ws[k][tx * 8];
            *(float4*)&rb[4] = *(const float4*)&Ws[k][tx * 8 + 4];
#pragma unroll
            for (int i = 0; i < 8; i++)
#pragma unroll
                for (int j = 0; j < 8; j++) acc[i][j] += ra[i] * rb[j];
        }
        __syncthreads();
    }

#pragma unroll
    for (int i = 0; i < 8; i++) {
        float* crow = C + (size_t)(m0 + ty * 8 + i) * N + n0 + tx * 8;
        *(float4*)(crow)     = make_float4(acc[i][0], acc[i][1], acc[i][2], acc[i][3]);
        *(float4*)(crow + 4) = make_float4(acc[i][4], acc[i][5], acc[i][6], acc[i][7]);
    }
}

// ---------------------------------------------------------------------------
// RoPE (in-place on Q and K). One thread per (token, head, d<64) pair.
// ---------------------------------------------------------------------------
__global__ __launch_bounds__(256) void rope_kernel(float* __restrict__ q,
                                                   float* __restrict__ k,
                                                   const int* __restrict__ pos_ids,
                                                   const float* __restrict__ rope) {
    int idx = blockIdx.x * blockDim.x + threadIdx.x;   // T_TOT*NHEAD*64
    int d = idx & 63;
    int h = (idx >> 6) & (NHEAD - 1);
    int t = idx >> 11;           // 0..4095
    if (t >= T_TOT) return;

    int s = pos_ids[t];
    float sn = rope[(size_t)s * 128 + d];
    float cs = rope[(size_t)s * 128 + 64 + d];

    size_t base = (size_t)t * HDIM + h * DHEAD + d;
    float q1 = q[base], q2 = q[base + 64];
    q[base]      = q1 * cs - q2 * sn;
    q[base + 64] = q2 * cs + q1 * sn;
    float k1 = k[base], k2 = k[base + 64];
    k[base]      = k1 * cs - k2 * sn;
    k[base + 64] = k2 * cs + k1 * sn;
}

// ---------------------------------------------------------------------------
// Fused causal flash attention, fp32. BQ=BK=64, D=128, 256 threads.
// Thread (r = tid/4, qd = tid%4): owns q-row r; score cols j = qd+4*jj;
// output cols c = qd*32 + [0..32).
// ---------------------------------------------------------------------------
__global__ __launch_bounds__(256) void attn_fused(const float* __restrict__ Q,
                                                  const float* __restrict__ K,
                                                  const float* __restrict__ V,
                                                  float* __restrict__ O) {
    extern __shared__ float sm[];
    float* Qs = sm;                 // [64][132]
    float* Ks = Qs + 64 * 132;      // [64][132]
    float* Vs = Ks + 64 * 132;      // [64][132]
    float* Ps = Vs + 64 * 132;      // [64][68]   (softmax probs)

    const int bh = blockIdx.y;
    const int b = bh >> 5;
    const int h = bh & (NHEAD - 1);
    const int q0 = blockIdx.x * 64;
    const int tid = threadIdx.x;
    const int r = tid >> 2;          // 0..63
    const int qd = tid & 3;          // 0..3

    const size_t rs = HDIM;
    const float* Qb = Q + (size_t)b * SEQ * rs + h * DHEAD;
    const float* Kb = K + (size_t)b * SEQ * rs + h * DHEAD;
    const float* Vb = V + (size_t)b * SEQ * rs + h * DHEAD;
    float* Ob = O + (size_t)b * SEQ * rs + h * DHEAD;

    // Load Q tile (row-major, padded)
#pragma unroll
    for (int it = 0; it < 8; it++) {
        int v = tid + it * 256;
        int row = v >> 5;           // 0..63
        int c4 = (v & 31) << 2;     // 0..124
        float4 x = *(const float4*)(Qb + (size_t)(q0 + row) * rs + c4);
        *(float4*)&Qs[row * 132 + c4] = x;
    }

    float4 acc4[8];
#pragma unroll
    for (int i = 0; i < 8; i++) acc4[i] = make_float4(0.f, 0.f, 0.f, 0.f);
    float mrow = -3.0e38f, lrow = 0.f;
    const float scale = 0.08838834764831845f;   // 1/sqrt(128)

    const int ntile = blockIdx.x + 1;
    for (int kt = 0; kt < ntile; kt++) {
        const int k0 = kt * 64;
        __syncthreads();   // protect Ks/Vs (and first-iter Qs) from overwrite
#pragma unroll
        for (int it = 0; it < 8; it++) {
            int v = tid + it * 256;
            int row = v >> 5;
            int c4 = (v & 31) << 2;
            float4 x = *(const float4*)(Kb + (size_t)(k0 + row) * rs + c4);
            *(float4*)&Ks[row * 132 + c4] = x;
            float4 y = *(const float4*)(Vb + (size_t)(k0 + row) * rs + c4);
            *(float4*)&Vs[row * 132 + c4] = y;
        }
        __syncthreads();

        // ---- scores: 16 j's per thread (j = qd + 4*jj), dot over 128 ----
        float sreg[16];
#pragma unroll
        for (int jj = 0; jj < 16; jj++) sreg[jj] = 0.f;
        const float* qrow = &Qs[r * 132];
#pragma unroll 8
        for (int kk4 = 0; kk4 < 32; kk4++) {
            float4 qv = *(const float4*)(qrow + kk4 * 4);
#pragma unroll
            for (int jj = 0; jj < 16; jj++) {
                const float4 kv = *(const float4*)&Ks[(qd + 4 * jj) * 132 + kk4 * 4];
                sreg[jj] += qv.x * kv.x + qv.y * kv.y + qv.z * kv.z + qv.w * kv.w;
            }
        }

        // scale + causal mask + tile max
        const int qg = q0 + r;
        float tm = -3.0e38f;
#pragma unroll
        for (int jj = 0; jj < 16; jj++) {
            int kg = k0 + qd + 4 * jj;
            float s = sreg[jj] * scale;
            if (kg > qg) s = -3.0e38f;
            sreg[jj] = s;
            tm = fmaxf(tm, s);
        }
        tm = fmaxf(tm, __shfl_xor_sync(0xffffffffu, tm, 1));
        tm = fmaxf(tm, __shfl_xor_sync(0xffffffffu, tm, 2));
        float mnew = fmaxf(mrow, tm);

        float psum = 0.f;
#pragma unroll
        for (int jj = 0; jj < 16; jj++) {
            float p = __expf(sreg[jj] - mnew);
            Ps[r * 68 + qd + 4 * jj] = p;
            psum += p;
        }
        psum += __shfl_xor_sync(0xffffffffu, psum, 1);
        psum += __shfl_xor_sync(0xffffffffu, psum, 2);

        float alpha = __expf(mrow - mnew);
        mrow = mnew;
        lrow = lrow * alpha + psum;
#pragma unroll
        for (int i = 0; i < 8; i++) {
            acc4[i].x *= alpha; acc4[i].y *= alpha;
            acc4[i].z *= alpha; acc4[i].w *= alpha;
        }
        __syncwarp();   // Ps row r fully written by this warp's quad before PV reads

        // ---- PV: acc[c] += sum_j p[r][j] * V[j][c],  c = qd*32 + [0..32) ----
        const float* vbase = &Vs[qd * 32];
        const float* prow = &Ps[r * 68];
#pragma unroll 4
        for (int j = 0; j < 64; j++) {
            float pj = prow[j];
            const float* vrow = vbase + j * 132;
#pragma unroll
            for (int i = 0; i < 8; i++) {
                float4 vv = *(const float4*)(vrow + i * 4);
                acc4[i].x += pj * vv.x; acc4[i].y += pj * vv.y;
                acc4[i].z += pj * vv.z; acc4[i].w += pj * vv.w;
            }
        }
    }

    float inv = 1.0f / lrow;
    float* orow = Ob + (size_t)(q0 + r) * rs + qd * 32;
#pragma unroll
    for (int i = 0; i < 8; i++) {
        float4 o = acc4[i];
        o.x *= inv; o.y *= inv; o.z *= inv; o.w *= inv;
        *(float4*)(orow + i * 4) = o;
    }
}

// ---------------------------------------------------------------------------
extern "C" void kernel_launch(void* const* d_in, const int* in_sizes, int n_in,
                              void* d_out, int out_size) {
    const float* hidden = (const float*)d_in[0];
    const int*   pos    = (const int*)d_in[1];
    // d_in[2]: attention_mask — exactly causal; applied analytically in attn_fused
    const float* Wq = (const float*)d_in[3];
    const float* Wk = (const float*)d_in[4];
    const float* Wv = (const float*)d_in[5];
    const float* Wo = (const float*)d_in[6];
    const float* rope = (const float*)d_in[7];
    float* out = (float*)d_out;

    float *q, *k, *v, *att;
    cudaGetSymbolAddress((void**)&q, g_q);
    cudaGetSymbolAddress((void**)&k, g_k);
    cudaGetSymbolAddress((void**)&v, g_v);
    cudaGetSymbolAddress((void**)&att, g_att);

    const int smem_attn = (3 * 64 * 132 + 64 * 68) * sizeof(float);  // 118784 B
    cudaFuncSetAttribute(attn_fused, cudaFuncAttributeMaxDynamicSharedMemorySize,
                         smem_attn);

    dim3 ggrid(HDIM / 128, T_TOT / 128);   // (32, 32)
    sgemm_tn<<<ggrid, 256>>>(hidden, Wq, q);
    sgemm_tn<<<ggrid, 256>>>(hidden, Wk, k);
    sgemm_tn<<<ggrid, 256>>>(hidden, Wv, v);

    int rope_threads = T_TOT * NHEAD * 64;   // 8,388,608
    rope_kernel<<<rope_threads / 256, 256>>>(q, k, pos, rope);

    dim3 agrid(SEQ / 64, 2 * NHEAD);         // (32, 64)
    attn_fused<<<agrid, 256, smem_attn>>>(q, k, v, att);

    sgemm_tn<<<ggrid, 256>>>(att, Wo, out);
}

// round 3
// speedup vs baseline: 1.5283x; 1.5283x over previous
#include <cuda_runtime.h>
#include <cuda_bf16.h>
#include <math.h>
#include <stdint.h>

#define T_TOT 4096   // B*S tokens
#define HDIM  4096   // hidden size
#define SEQ   2048
#define NHEAD 32
#define DHEAD 128
#define KP    12288  // split-K: 3 * HDIM

// ---------------- scratch (device globals; no allocations allowed) ----------
__device__ float g_q[(size_t)T_TOT * HDIM];
__device__ float g_k[(size_t)T_TOT * HDIM];
__device__ float g_v[(size_t)T_TOT * HDIM];
__device__ float g_att[(size_t)T_TOT * HDIM];
__device__ __nv_bfloat16 g_hidA[(size_t)T_TOT * KP];
__device__ __nv_bfloat16 g_attA[(size_t)T_TOT * KP];
__device__ __nv_bfloat16 g_wqS[(size_t)HDIM * KP];
__device__ __nv_bfloat16 g_wkS[(size_t)HDIM * KP];
__device__ __nv_bfloat16 g_wvS[(size_t)HDIM * KP];
__device__ __nv_bfloat16 g_woS[(size_t)HDIM * KP];

// ---------------- helpers ----------------------------------------------------
__device__ __forceinline__ uint32_t smem_u32(const void* p) {
    uint32_t a;
    asm("{ .reg .u64 t; cvta.to.shared.u64 t, %1; cvt.u32.u64 %0, t; }"
        : "=r"(a) : "l"(p));
    return a;
}
#define CP_ASYNC16(dst, src) \
    asm volatile("cp.async.cg.shared.global [%0], [%1], 16;" :: "r"(dst), "l"(src))
#define CP_COMMIT()  asm volatile("cp.async.commit_group;" ::: "memory")
#define CP_WAIT(n)   asm volatile("cp.async.wait_group %0;" :: "n"(n) : "memory")

#define LDSM_X4(r0, r1, r2, r3, addr)                                        \
    asm volatile("ldmatrix.sync.aligned.m8n8.x4.shared.b16 {%0,%1,%2,%3}, [%4];" \
        : "=r"(r0), "=r"(r1), "=r"(r2), "=r"(r3) : "r"(addr))

#define MMA_BF16(d, a, b)                                                    \
    asm volatile("mma.sync.aligned.m16n8k16.row.col.f32.bf16.bf16.f32 "      \
        "{%0,%1,%2,%3}, {%4,%5,%6,%7}, {%8,%9}, {%0,%1,%2,%3};"              \
        : "+f"((d)[0]), "+f"((d)[1]), "+f"((d)[2]), "+f"((d)[3])             \
        : "r"((a)[0]), "r"((a)[1]), "r"((a)[2]), "r"((a)[3]),                \
          "r"((b)[0]), "r"((b)[1]))

// ---------------------------------------------------------------------------
// split3: fp32 [R,4096] -> bf16 [R,12288].
// mode 0 (activations): [hi | hi | lo];  mode 1 (weights): [hi | lo | hi]
// so that sum over K' = ah*bh + ah*bl + al*bh.
// ---------------------------------------------------------------------------
__global__ __launch_bounds__(256) void split3(const float* __restrict__ src,
                                              __nv_bfloat16* __restrict__ dst,
                                              int wmode) {
    int idx = blockIdx.x * 256 + threadIdx.x;
    int row = idx >> 10;
    int cg = (idx & 1023) << 2;
    float4 x = *(const float4*)(src + (size_t)row * 4096 + cg);
    float xs[4] = {x.x, x.y, x.z, x.w};
    __nv_bfloat16 h[4], l[4];
#pragma unroll
    for (int i = 0; i < 4; i++) {
        h[i] = __float2bfloat16(xs[i]);
        l[i] = __float2bfloat16(xs[i] - __bfloat162float(h[i]));
    }
    __nv_bfloat162 hp0 = __halves2bfloat162(h[0], h[1]);
    __nv_bfloat162 hp1 = __halves2bfloat162(h[2], h[3]);
    __nv_bfloat162 lp0 = __halves2bfloat162(l[0], l[1]);
    __nv_bfloat162 lp1 = __halves2bfloat162(l[2], l[3]);
    __nv_bfloat16* d0 = dst + (size_t)row * KP + cg;
    *(__nv_bfloat162*)(d0)     = hp0;
    *(__nv_bfloat162*)(d0 + 2) = hp1;
    if (wmode) {
        *(__nv_bfloat162*)(d0 + 4096) = lp0; *(__nv_bfloat162*)(d0 + 4098) = lp1;
        *(__nv_bfloat162*)(d0 + 8192) = hp0; *(__nv_bfloat162*)(d0 + 8194) = hp1;
    } else {
        *(__nv_bfloat162*)(d0 + 4096) = hp0; *(__nv_bfloat162*)(d0 + 4098) = hp1;
        *(__nv_bfloat162*)(d0 + 8192) = lp0; *(__nv_bfloat162*)(d0 + 8194) = lp1;
    }
}

// ---------------------------------------------------------------------------
// mma.sync bf16 GEMM: C[m,n] = sum_k A[m,k]*B[n,k]
// A:[4096,KP] bf16 row-major, B:[4096,KP] bf16 row-major, C fp32 [4096,4096].
// Tile 128x128, BK=32, 8 warps (each 32x64), 3-stage cp.async pipeline.
// smem layout per stage: A 128 rows x 64B, then B 128 rows x 64B;
// 16B-chunk swizzle: chunk ^= (row>>1)&3  (conflict-free ldmatrix + stores).
// ---------------------------------------------------------------------------
#define KT (KP / 32)          // 384 k-tiles
#define STG 16384             // bytes per stage (A 8K + B 8K)

__device__ __forceinline__ void g_load_stage(const __nv_bfloat16* __restrict__ A,
                                             const __nv_bfloat16* __restrict__ B,
                                             int m0, int n0, int kt,
                                             uint32_t stg, int tid) {
    const __nv_bfloat16* ga = A + (size_t)m0 * KP + kt * 32;
    const __nv_bfloat16* gb = B + (size_t)n0 * KP + kt * 32;
#pragma unroll
    for (int i = 0; i < 2; i++) {
        int ci = tid + i * 256;            // 0..511
        int r = ci >> 2, c = ci & 3;
        uint32_t sw = (uint32_t)(c ^ ((r >> 1) & 3)) << 4;
        CP_ASYNC16(stg + r * 64 + sw, ga + (size_t)r * KP + c * 8);
        CP_ASYNC16(stg + 8192 + r * 64 + sw, gb + (size_t)r * KP + c * 8);
    }
    CP_COMMIT();
}

__global__ __launch_bounds__(256, 2) void gemm_mma(const __nv_bfloat16* __restrict__ A,
                                                   const __nv_bfloat16* __restrict__ B,
                                                   float* __restrict__ C) {
    __shared__ __align__(128) char smem[3 * STG];

    const int tid = threadIdx.x, lane = tid & 31, wid = tid >> 5;
    const int m0 = blockIdx.y * 128, n0 = blockIdx.x * 128;
    const int wm = (wid >> 1) * 32;      // warp m offset: 0,32,64,96
    const int wn = (wid & 1) * 64;       // warp n offset: 0,64

    const uint32_t sbase = smem_u32(smem);

    // per-lane ldmatrix geometry
    const int rA = wm + (lane & 15);              // A row for this lane
    const int cA = lane >> 4;                     // chunk offset 0/1
    const int keyA = (rA >> 1) & 3;
    const int rB = (lane & 7) + ((lane >> 4) << 3);  // 0..15 within n-pair
    const int cB = (lane >> 3) & 1;
    const int keyB = ((wn + rB) >> 1) & 3;

    float acc[2][8][4];
#pragma unroll
    for (int mt = 0; mt < 2; mt++)
#pragma unroll
        for (int nt = 0; nt < 8; nt++)
#pragma unroll
            for (int e = 0; e < 4; e++) acc[mt][nt][e] = 0.f;

    g_load_stage(A, B, m0, n0, 0, sbase, tid);
    g_load_stage(A, B, m0, n0, 1, sbase + STG, tid);

    for (int kt = 0; kt < KT; kt++) {
        if (kt + 2 < KT) { CP_WAIT(1); } else { CP_WAIT(0); }
        __syncthreads();
        if (kt + 2 < KT)
            g_load_stage(A, B, m0, n0, kt + 2, sbase + ((kt + 2) % 3) * STG, tid);

        const uint32_t st = sbase + (kt % 3) * STG;
        const uint32_t aAddr = st + rA * 64;
        const uint32_t bAddr = st + 8192 + (wn + rB) * 64;

#pragma unroll
        for (int ks = 0; ks < 2; ks++) {
            uint32_t aF[2][4];
#pragma unroll
            for (int mt = 0; mt < 2; mt++) {
                uint32_t ad = aAddr + mt * 1024 +
                              (((ks * 2 + cA) ^ keyA) << 4);
                LDSM_X4(aF[mt][0], aF[mt][1], aF[mt][2], aF[mt][3], ad);
            }
            uint32_t bF[8][2];
#pragma unroll
            for (int np = 0; np < 4; np++) {
                uint32_t bd = bAddr + np * 1024 +
                              (((ks * 2 + cB) ^ keyB) << 4);
                LDSM_X4(bF[2 * np][0], bF[2 * np][1],
                        bF[2 * np + 1][0], bF[2 * np + 1][1], bd);
            }
#pragma unroll
            for (int mt = 0; mt < 2; mt++)
#pragma unroll
                for (int nt = 0; nt < 8; nt++)
                    MMA_BF16(acc[mt][nt], aF[mt], bF[nt]);
        }
    }

    // epilogue: direct fp32 stores (float2 per 8-row piece)
    const int cbase = n0 + wn + ((lane & 3) << 1);
#pragma unroll
    for (int mt = 0; mt < 2; mt++) {
        int r0 = m0 + wm + mt * 16 + (lane >> 2);
#pragma unroll
        for (int nt = 0; nt < 8; nt++) {
            float* p0 = C + (size_t)r0 * HDIM + cbase + nt * 8;
            float* p1 = p0 + 8 * HDIM;
            *(float2*)p0 = make_float2(acc[mt][nt][0], acc[mt][nt][1]);
            *(float2*)p1 = make_float2(acc[mt][nt][2], acc[mt][nt][3]);
        }
    }
}

// ---------------------------------------------------------------------------
// RoPE (in-place on Q and K), fp32
// ---------------------------------------------------------------------------
__global__ __launch_bounds__(256) void rope_kernel(float* __restrict__ q,
                                                   float* __restrict__ k,
                                                   const int* __restrict__ pos_ids,
                                                   const float* __restrict__ rope) {
    int idx = blockIdx.x * blockDim.x + threadIdx.x;
    int d = idx & 63;
    int h = (idx >> 6) & (NHEAD - 1);
    int t = idx >> 11;
    if (t >= T_TOT) return;
    int s = pos_ids[t];
    float sn = rope[(size_t)s * 128 + d];
    float cs = rope[(size_t)s * 128 + 64 + d];
    size_t base = (size_t)t * HDIM + h * DHEAD + d;
    float q1 = q[base], q2 = q[base + 64];
    q[base]      = q1 * cs - q2 * sn;
    q[base + 64] = q2 * cs + q1 * sn;
    float k1 = k[base], k2 = k[base + 64];
    k[base]      = k1 * cs - k2 * sn;
    k[base + 64] = k2 * cs + k1 * sn;
}

// ---------------------------------------------------------------------------
// Fused causal flash attention, fp32 (unchanged — known correct)
// ---------------------------------------------------------------------------
__global__ __launch_bounds__(256) void attn_fused(const float* __restrict__ Q,
                                                  const float* __restrict__ K,
                                                  const float* __restrict__ V,
                                                  float* __restrict__ O) {
    extern __shared__ float sm[];
    float* Qs = sm;
    float* Ks = Qs + 64 * 132;
    float* Vs = Ks + 64 * 132;
    float* Ps = Vs + 64 * 132;

    const int bh = blockIdx.y;
    const int b = bh >> 5;
    const int h = bh & (NHEAD - 1);
    const int q0 = blockIdx.x * 64;
    const int tid = threadIdx.x;
    const int r = tid >> 2;
    const int qd = tid & 3;

    const size_t rs = HDIM;
    const float* Qb = Q + (size_t)b * SEQ * rs + h * DHEAD;
    const float* Kb = K + (size_t)b * SEQ * rs + h * DHEAD;
    const float* Vb = V + (size_t)b * SEQ * rs + h * DHEAD;
    float* Ob = O + (size_t)b * SEQ * rs + h * DHEAD;

#pragma unroll
    for (int it = 0; it < 8; it++) {
        int v = tid + it * 256;
        int row = v >> 5;
        int c4 = (v & 31) << 2;
        float4 x = *(const float4*)(Qb + (size_t)(q0 + row) * rs + c4);
        *(float4*)&Qs[row * 132 + c4] = x;
    }

    float4 acc4[8];
#pragma unroll
    for (int i = 0; i < 8; i++) acc4[i] = make_float4(0.f, 0.f, 0.f, 0.f);
    float mrow = -3.0e38f, lrow = 0.f;
    const float scale = 0.08838834764831845f;

    const int ntile = blockIdx.x + 1;
    for (int kt = 0; kt < ntile; kt++) {
        const int k0 = kt * 64;
        __syncthreads();
#pragma unroll
        for (int it = 0; it < 8; it++) {
            int v = tid + it * 256;
            int row = v >> 5;
            int c4 = (v & 31) << 2;
            float4 x = *(const float4*)(Kb + (size_t)(k0 + row) * rs + c4);
            *(float4*)&Ks[row * 132 + c4] = x;
            float4 y = *(const float4*)(Vb + (size_t)(k0 + row) * rs + c4);
            *(float4*)&Vs[row * 132 + c4] = y;
        }
        __syncthreads();

        float sreg[16];
#pragma unroll
        for (int jj = 0; jj < 16; jj++) sreg[jj] = 0.f;
        const float* qrow = &Qs[r * 132];
#pragma unroll 8
        for (int kk4 = 0; kk4 < 32; kk4++) {
            float4 qv = *(const float4*)(qrow + kk4 * 4);
#pragma unroll
            for (int jj = 0; jj < 16; jj++) {
                const float4 kv = *(const float4*)&Ks[(qd + 4 * jj) * 132 + kk4 * 4];
                sreg[jj] += qv.x * kv.x + qv.y * kv.y + qv.z * kv.z + qv.w * kv.w;
            }
        }

        const int qg = q0 + r;
        float tm = -3.0e38f;
#pragma unroll
        for (int jj = 0; jj < 16; jj++) {
            int kg = k0 + qd + 4 * jj;
            float s = sreg[jj] * scale;
            if (kg > qg) s = -3.0e38f;
            sreg[jj] = s;
            tm = fmaxf(tm, s);
        }
        tm = fmaxf(tm, __shfl_xor_sync(0xffffffffu, tm, 1));
        tm = fmaxf(tm, __shfl_xor_sync(0xffffffffu, tm, 2));
        float mnew = fmaxf(mrow, tm);

        float psum = 0.f;
#pragma unroll
        for (int jj = 0; jj < 16; jj++) {
            float p = __expf(sreg[jj] - mnew);
            Ps[r * 68 + qd + 4 * jj] = p;
            psum += p;
        }
        psum += __shfl_xor_sync(0xffffffffu, psum, 1);
        psum += __shfl_xor_sync(0xffffffffu, psum, 2);

        float alpha = __expf(mrow - mnew);
        mrow = mnew;
        lrow = lrow * alpha + psum;
#pragma unroll
        for (int i = 0; i < 8; i++) {
            acc4[i].x *= alpha; acc4[i].y *= alpha;
            acc4[i].z *= alpha; acc4[i].w *= alpha;
        }
        __syncwarp();

        const float* vbase = &Vs[qd * 32];
        const float* prow = &Ps[r * 68];
#pragma unroll 4
        for (int j = 0; j < 64; j++) {
            float pj = prow[j];
            const float* vrow = vbase + j * 132;
#pragma unroll
            for (int i = 0; i < 8; i++) {
                float4 vv = *(const float4*)(vrow + i * 4);
                acc4[i].x += pj * vv.x; acc4[i].y += pj * vv.y;
                acc4[i].z += pj * vv.z; acc4[i].w += pj * vv.w;
            }
        }
    }

    float inv = 1.0f / lrow;
    float* orow = Ob + (size_t)(q0 + r) * rs + qd * 32;
#pragma unroll
    for (int i = 0; i < 8; i++) {
        float4 o = acc4[i];
        o.x *= inv; o.y *= inv; o.z *= inv; o.w *= inv;
        *(float4*)(orow + i * 4) = o;
    }
}

// ---------------------------------------------------------------------------
extern "C" void kernel_launch(void* const* d_in, const int* in_sizes, int n_in,
                              void* d_out, int out_size) {
    const float* hidden = (const float*)d_in[0];
    const int*   pos    = (const int*)d_in[1];
    // d_in[2]: attention_mask — exactly causal; applied analytically
    const float* Wq = (const float*)d_in[3];
    const float* Wk = (const float*)d_in[4];
    const float* Wv = (const float*)d_in[5];
    const float* Wo = (const float*)d_in[6];
    const float* rope = (const float*)d_in[7];
    float* out = (float*)d_out;

    float *q, *k, *v, *att;
    __nv_bfloat16 *hidA, *attA, *wq, *wk, *wv, *wo;
    cudaGetSymbolAddress((void**)&q, g_q);
    cudaGetSymbolAddress((void**)&k, g_k);
    cudaGetSymbolAddress((void**)&v, g_v);
    cudaGetSymbolAddress((void**)&att, g_att);
    cudaGetSymbolAddress((void**)&hidA, g_hidA);
    cudaGetSymbolAddress((void**)&attA, g_attA);
    cudaGetSymbolAddress((void**)&wq, g_wqS);
    cudaGetSymbolAddress((void**)&wk, g_wkS);
    cudaGetSymbolAddress((void**)&wv, g_wvS);
    cudaGetSymbolAddress((void**)&wo, g_woS);

    const int smem_attn = (3 * 64 * 132 + 64 * 68) * sizeof(float);
    cudaFuncSetAttribute(attn_fused, cudaFuncAttributeMaxDynamicSharedMemorySize,
                         smem_attn);

    const int sgrid = T_TOT * HDIM / 4 / 256;   // 16384
    split3<<<sgrid, 256>>>(hidden, hidA, 0);
    split3<<<sgrid, 256>>>(Wq, wq, 1);
    split3<<<sgrid, 256>>>(Wk, wk, 1);
    split3<<<sgrid, 256>>>(Wv, wv, 1);
    split3<<<sgrid, 256>>>(Wo, wo, 1);

    dim3 ggrid(HDIM / 128, T_TOT / 128);        // (32, 32)
    gemm_mma<<<ggrid, 256>>>(hidA, wq, q);
    gemm_mma<<<ggrid, 256>>>(hidA, wk, k);
    gemm_mma<<<ggrid, 256>>>(hidA, wv, v);

    rope_kernel<<<(T_TOT * NHEAD * 64) / 256, 256>>>(q, k, pos, rope);

    dim3 agrid(SEQ / 64, 2 * NHEAD);
    attn_fused<<<agrid, 256, smem_attn>>>(q, k, v, att);

    split3<<<sgrid, 256>>>(att, attA, 0);
    gemm_mma<<<ggrid, 256>>>(attA, wo, out);
}